// round 2
// baseline (speedup 1.0000x reference)
#include <cuda_runtime.h>
#include <math.h>
#include <stdint.h>

#define N_NODES 50000
#define N_EDGES 800000
#define N_CLUST 5000
#define GRID_SMS 152

// ---------------- static device scratch (no allocations allowed) ----------------
__device__ __align__(16) float g_x1[N_NODES * 128];   // layer0 out: [h2(64) | agg(64)]
__device__ __align__(16) float g_x2[N_NODES * 256];   // layer1 out
__device__ __align__(16) float g_x3[N_NODES * 512];   // layer2 out
__device__ __align__(16) float g_pooled[N_CLUST * 512];
__device__ __align__(16) float g_partial[64 * 512];
__device__ __align__(16) float g_norms[512];

__device__ int g_deg[N_NODES];
__device__ int g_rowptr[N_NODES + 1];
__device__ int g_cursor[N_NODES];
__device__ int g_esrc[N_EDGES];
__device__ int g_cdeg[N_CLUST];
__device__ int g_crow[N_CLUST + 1];
__device__ int g_ccur[N_CLUST];
__device__ int g_cnodes[N_NODES];

__device__ __forceinline__ float4 fmax4(float4 a, float4 b) {
    return make_float4(fmaxf(a.x, b.x), fmaxf(a.y, b.y), fmaxf(a.z, b.z), fmaxf(a.w, b.w));
}

// ---------------- CSR build ----------------
__global__ void zero_counts_k() {
    int i = blockIdx.x * blockDim.x + threadIdx.x;
    if (i < N_NODES) g_deg[i] = 0;
    if (i < N_CLUST) g_cdeg[i] = 0;
}

__global__ void hist_edges_k(const int* __restrict__ dst) {
    int e = blockIdx.x * blockDim.x + threadIdx.x;
    if (e < N_EDGES) atomicAdd(&g_deg[dst[e]], 1);
}

__global__ void hist_clusters_k(const int* __restrict__ clu) {
    int n = blockIdx.x * blockDim.x + threadIdx.x;
    if (n < N_NODES) atomicAdd(&g_cdeg[clu[n]], 1);
}

// single-block exclusive scan; sel=0: deg->rowptr (N), sel=1: cdeg->crow (NC)
__global__ void scan_k(int sel) {
    const int* in = sel ? g_cdeg : g_deg;
    int* out = sel ? g_crow : g_rowptr;
    int n = sel ? N_CLUST : N_NODES;
    __shared__ int sh[1024];
    int t = threadIdx.x;
    int items = (n + 1023) >> 10;
    int beg = t * items; if (beg > n) beg = n;
    int end = beg + items; if (end > n) end = n;
    int s = 0;
    for (int i = beg; i < end; i++) s += in[i];
    sh[t] = s;
    __syncthreads();
    for (int o = 1; o < 1024; o <<= 1) {
        int v = (t >= o) ? sh[t - o] : 0;
        __syncthreads();
        sh[t] += v;
        __syncthreads();
    }
    int run = sh[t] - s;  // exclusive prefix
    for (int i = beg; i < end; i++) { out[i] = run; run += in[i]; }
    if (t == 1023) out[n] = sh[1023];
}

__global__ void copy_cursors_k() {
    int i = blockIdx.x * blockDim.x + threadIdx.x;
    if (i < N_NODES) g_cursor[i] = g_rowptr[i];
    if (i < N_CLUST) g_ccur[i] = g_crow[i];
}

__global__ void fill_edges_k(const int* __restrict__ src, const int* __restrict__ dst) {
    int e = blockIdx.x * blockDim.x + threadIdx.x;
    if (e < N_EDGES) {
        int d = dst[e];
        int slot = atomicAdd(&g_cursor[d], 1);
        g_esrc[slot] = src[e];
    }
}

__global__ void fill_clusters_k(const int* __restrict__ clu) {
    int n = blockIdx.x * blockDim.x + threadIdx.x;
    if (n < N_NODES) {
        int c = clu[n];
        int slot = atomicAdd(&g_ccur[c], 1);
        g_cnodes[slot] = n;
    }
}

// ---------------- per-node MLP: Linear(CIN->64) -> LN -> ReLU -> Linear(64->CIN) ----------------
// one warp processes NB nodes; lane owns columns j={2L,2L+1} in h-space and
// c=[CPL*L, CPL*L+CPL) in out-space. Weights in dynamic smem, persistent grid.
template <int CIN, int NW, int NB>
__global__ void __launch_bounds__(NW * 32, 1) mlp_k(
    const float* __restrict__ xin_ext,
    const float* __restrict__ w1, const float* __restrict__ b1,
    const float* __restrict__ gg, const float* __restrict__ be,
    const float* __restrict__ w2, const float* __restrict__ b2)
{
    constexpr int CPL = CIN / 32;
    const float* xin;
    float* xout;
    if constexpr (CIN == 64)       { xin = xin_ext; xout = g_x1; }
    else if constexpr (CIN == 128) { xin = g_x1;    xout = g_x2; }
    else                           { xin = g_x2;    xout = g_x3; }

    extern __shared__ float smem[];
    float* w1s = smem;             // [CIN][64]
    float* w2s = smem + CIN * 64;  // [64][CIN]
    int tid = threadIdx.x;
    int L = tid & 31;
    int w = tid >> 5;
    float* xs = smem + CIN * 128 + w * (NB * CIN);  // per-warp x rows / h storage

    for (int i = tid; i < CIN * 64; i += NW * 32) { w1s[i] = w1[i]; w2s[i] = w2[i]; }
    __syncthreads();

    float b1a = b1[2 * L], b1b = b1[2 * L + 1];
    float ga = gg[2 * L], gb = gg[2 * L + 1];
    float bea = be[2 * L], beb = be[2 * L + 1];
    float b2r[CPL];
#pragma unroll
    for (int k = 0; k < CPL; k++) b2r[k] = b2[CPL * L + k];

    const int ntasks = (N_NODES + NB - 1) / NB;
    for (int task = blockIdx.x * NW + w; task < ntasks; task += gridDim.x * NW) {
        int n0 = task * NB;
        // stage x rows into smem (coalesced float4)
#pragma unroll
        for (int b = 0; b < NB; b++) {
            int n = n0 + b;
            if (n < N_NODES) {
                const float4* xr = reinterpret_cast<const float4*>(xin + (size_t)n * CIN);
                float4* xd = reinterpret_cast<float4*>(xs + b * CIN);
                for (int k = L; k < CIN / 4; k += 32) xd[k] = xr[k];
            }
        }
        __syncwarp();

        // ---- h = x @ w1 + b1 ----
        float a0[NB], a1[NB];
#pragma unroll
        for (int b = 0; b < NB; b++) { a0[b] = b1a; a1[b] = b1b; }
#pragma unroll 2
        for (int c = 0; c < CIN; c += 4) {
            float4 xv[NB];
#pragma unroll
            for (int b = 0; b < NB; b++) xv[b] = *reinterpret_cast<const float4*>(&xs[b * CIN + c]);
#pragma unroll
            for (int u = 0; u < 4; u++) {
                float2 wv = *reinterpret_cast<const float2*>(&w1s[(c + u) * 64 + 2 * L]);
#pragma unroll
                for (int b = 0; b < NB; b++) {
                    float xb = (u == 0) ? xv[b].x : (u == 1) ? xv[b].y : (u == 2) ? xv[b].z : xv[b].w;
                    a0[b] = fmaf(xb, wv.x, a0[b]);
                    a1[b] = fmaf(xb, wv.y, a1[b]);
                }
            }
        }

        // ---- LayerNorm(64) + ReLU ----
        float h0[NB], h1[NB];
#pragma unroll
        for (int b = 0; b < NB; b++) {
            float s = a0[b] + a1[b];
#pragma unroll
            for (int o = 16; o > 0; o >>= 1) s += __shfl_xor_sync(0xffffffffu, s, o);
            float mu = s * (1.0f / 64.0f);
            float e0 = a0[b] - mu, e1 = a1[b] - mu;
            float q = e0 * e0 + e1 * e1;
#pragma unroll
            for (int o = 16; o > 0; o >>= 1) q += __shfl_xor_sync(0xffffffffu, q, o);
            float rs = rsqrtf(q * (1.0f / 64.0f) + 1e-5f);
            h0[b] = fmaxf(fmaf(e0 * rs, ga, bea), 0.0f);
            h1[b] = fmaxf(fmaf(e1 * rs, gb, beb), 0.0f);
        }
        __syncwarp();
#pragma unroll
        for (int b = 0; b < NB; b++)
            *reinterpret_cast<float2*>(&xs[b * CIN + 2 * L]) = make_float2(h0[b], h1[b]);
        __syncwarp();

        // ---- out = h @ w2 + b2 ----
        float acc[NB][CPL];
#pragma unroll
        for (int b = 0; b < NB; b++)
#pragma unroll
            for (int k = 0; k < CPL; k++) acc[b][k] = b2r[k];

#pragma unroll 2
        for (int j = 0; j < 64; j += 4) {
            float4 hv[NB];
#pragma unroll
            for (int b = 0; b < NB; b++) hv[b] = *reinterpret_cast<const float4*>(&xs[b * CIN + j]);
#pragma unroll
            for (int u = 0; u < 4; u++) {
                if constexpr (CPL >= 4) {
#pragma unroll
                    for (int k = 0; k < CPL; k += 4) {
                        float4 wv = *reinterpret_cast<const float4*>(&w2s[(j + u) * CIN + CPL * L + k]);
#pragma unroll
                        for (int b = 0; b < NB; b++) {
                            float hb = (u == 0) ? hv[b].x : (u == 1) ? hv[b].y : (u == 2) ? hv[b].z : hv[b].w;
                            acc[b][k + 0] = fmaf(hb, wv.x, acc[b][k + 0]);
                            acc[b][k + 1] = fmaf(hb, wv.y, acc[b][k + 1]);
                            acc[b][k + 2] = fmaf(hb, wv.z, acc[b][k + 2]);
                            acc[b][k + 3] = fmaf(hb, wv.w, acc[b][k + 3]);
                        }
                    }
                } else {
                    float2 wv = *reinterpret_cast<const float2*>(&w2s[(j + u) * CIN + 2 * L]);
#pragma unroll
                    for (int b = 0; b < NB; b++) {
                        float hb = (u == 0) ? hv[b].x : (u == 1) ? hv[b].y : (u == 2) ? hv[b].z : hv[b].w;
                        acc[b][0] = fmaf(hb, wv.x, acc[b][0]);
                        acc[b][1] = fmaf(hb, wv.y, acc[b][1]);
                    }
                }
            }
        }

        // write h2 into first half of the concat row
#pragma unroll
        for (int b = 0; b < NB; b++) {
            int n = n0 + b;
            if (n < N_NODES) {
                float* orow = xout + (size_t)n * (2 * CIN) + CPL * L;
                if constexpr (CPL >= 4) {
#pragma unroll
                    for (int k = 0; k < CPL; k += 4)
                        *reinterpret_cast<float4*>(orow + k) =
                            make_float4(acc[b][k], acc[b][k + 1], acc[b][k + 2], acc[b][k + 3]);
                } else {
                    *reinterpret_cast<float2*>(orow) = make_float2(acc[b][0], acc[b][1]);
                }
            }
        }
        __syncwarp();
    }
}

// ---------------- scatter-max via CSR gather: warp per dst node ----------------
template <int CIN>
__global__ void agg_k() {
    constexpr int CPL = CIN / 32;
    float* xbuf;
    if constexpr (CIN == 64)       xbuf = g_x1;
    else if constexpr (CIN == 128) xbuf = g_x2;
    else                           xbuf = g_x3;

    int gw = (blockIdx.x * blockDim.x + threadIdx.x) >> 5;
    int L = threadIdx.x & 31;
    if (gw >= N_NODES) return;
    int beg = g_rowptr[gw], end = g_rowptr[gw + 1];
    const float NEG = __int_as_float(0xff800000);  // -inf

    if constexpr (CPL == 2) {
        float2 m = make_float2(NEG, NEG);
        int e = beg;
        for (; e + 2 <= end; e += 2) {
            int s0 = g_esrc[e], s1 = g_esrc[e + 1];
            float2 v0 = *reinterpret_cast<const float2*>(xbuf + (size_t)s0 * (2 * CIN) + 2 * L);
            float2 v1 = *reinterpret_cast<const float2*>(xbuf + (size_t)s1 * (2 * CIN) + 2 * L);
            m.x = fmaxf(m.x, fmaxf(v0.x, v1.x));
            m.y = fmaxf(m.y, fmaxf(v0.y, v1.y));
        }
        if (e < end) {
            int s0 = g_esrc[e];
            float2 v0 = *reinterpret_cast<const float2*>(xbuf + (size_t)s0 * (2 * CIN) + 2 * L);
            m.x = fmaxf(m.x, v0.x);
            m.y = fmaxf(m.y, v0.y);
        }
        if (beg == end) { m.x = 0.0f; m.y = 0.0f; }
        *reinterpret_cast<float2*>(xbuf + (size_t)gw * (2 * CIN) + CIN + 2 * L) = m;
    } else {
        constexpr int V = CPL / 4;
        float4 m[V];
#pragma unroll
        for (int k = 0; k < V; k++) m[k] = make_float4(NEG, NEG, NEG, NEG);
        int e = beg;
        for (; e + 2 <= end; e += 2) {
            int s0 = g_esrc[e], s1 = g_esrc[e + 1];
            const float4* r0 = reinterpret_cast<const float4*>(xbuf + (size_t)s0 * (2 * CIN) + CPL * L);
            const float4* r1 = reinterpret_cast<const float4*>(xbuf + (size_t)s1 * (2 * CIN) + CPL * L);
#pragma unroll
            for (int k = 0; k < V; k++) m[k] = fmax4(m[k], fmax4(r0[k], r1[k]));
        }
        if (e < end) {
            int s0 = g_esrc[e];
            const float4* r0 = reinterpret_cast<const float4*>(xbuf + (size_t)s0 * (2 * CIN) + CPL * L);
#pragma unroll
            for (int k = 0; k < V; k++) m[k] = fmax4(m[k], r0[k]);
        }
        if (beg == end) {
#pragma unroll
            for (int k = 0; k < V; k++) m[k] = make_float4(0.f, 0.f, 0.f, 0.f);
        }
        float4* o = reinterpret_cast<float4*>(xbuf + (size_t)gw * (2 * CIN) + CIN + CPL * L);
#pragma unroll
        for (int k = 0; k < V; k++) o[k] = m[k];
    }
}

// ---------------- cluster max-pool: warp per cluster, 512 channels ----------------
__global__ void pool_k() {
    int gw = (blockIdx.x * blockDim.x + threadIdx.x) >> 5;
    int L = threadIdx.x & 31;
    if (gw >= N_CLUST) return;
    int beg = g_crow[gw], end = g_crow[gw + 1];
    const float NEG = __int_as_float(0xff800000);
    float4 m[4];
#pragma unroll
    for (int k = 0; k < 4; k++) m[k] = make_float4(NEG, NEG, NEG, NEG);
    for (int e = beg; e < end; e++) {
        int n = g_cnodes[e];
        const float4* r = reinterpret_cast<const float4*>(g_x3 + (size_t)n * 512 + 16 * L);
#pragma unroll
        for (int k = 0; k < 4; k++) m[k] = fmax4(m[k], r[k]);
    }
    if (beg == end) {
#pragma unroll
        for (int k = 0; k < 4; k++) m[k] = make_float4(0.f, 0.f, 0.f, 0.f);
    }
    float4* o = reinterpret_cast<float4*>(g_pooled + (size_t)gw * 512 + 16 * L);
#pragma unroll
    for (int k = 0; k < 4; k++) o[k] = m[k];
}

// ---------------- column L2 norm (deterministic 2-stage) + scale ----------------
__global__ void colsum_k() {  // grid 64, block 512
    int b = blockIdx.x, c = threadIdx.x;
    int per = (N_CLUST + 63) / 64;
    int r0 = b * per;
    int r1 = r0 + per; if (r1 > N_CLUST) r1 = N_CLUST;
    float s = 0.0f;
    for (int r = r0; r < r1; r++) {
        float v = g_pooled[(size_t)r * 512 + c];
        s = fmaf(v, v, s);
    }
    g_partial[b * 512 + c] = s;
}

__global__ void norm_k() {  // 1 block, 512 threads
    int c = threadIdx.x;
    float s = 0.0f;
    for (int b = 0; b < 64; b++) s += g_partial[b * 512 + c];
    g_norms[c] = sqrtf(s);
}

__global__ void scale_k(float* __restrict__ out) {
    int idx = blockIdx.x * blockDim.x + threadIdx.x;
    if (idx < N_CLUST * 512) out[idx] = g_pooled[idx] / g_norms[idx & 511];
}

// ---------------- launch ----------------
extern "C" void kernel_launch(void* const* d_in, const int* in_sizes, int n_in,
                              void* d_out, int out_size) {
    const float* x = (const float*)d_in[0];
    const int* eidx = (const int*)d_in[1];   // int32: JAX default x64-disabled
    const int* clu = (const int*)d_in[2];
    int base = n_in - 18;  // 18 parameter tensors are the LAST inputs
    const float* P[18];
    for (int i = 0; i < 18; i++) P[i] = (const float*)d_in[base + i];
    const int* src = eidx;
    const int* dst = eidx + N_EDGES;
    float* out = (float*)d_out;

    constexpr int NW = 16, NB = 4;
    const int smem0 = 64 * 192 * 4;    //  49152
    const int smem1 = 128 * 192 * 4;   //  98304
    const int smem2 = 256 * 192 * 4;   // 196608
    cudaFuncSetAttribute(mlp_k<64, NW, NB>,  cudaFuncAttributeMaxDynamicSharedMemorySize, smem0);
    cudaFuncSetAttribute(mlp_k<128, NW, NB>, cudaFuncAttributeMaxDynamicSharedMemorySize, smem1);
    cudaFuncSetAttribute(mlp_k<256, NW, NB>, cudaFuncAttributeMaxDynamicSharedMemorySize, smem2);

    // CSR build (edges by dst, nodes by cluster)
    zero_counts_k<<<196, 256>>>();
    hist_edges_k<<<3125, 256>>>(dst);
    hist_clusters_k<<<196, 256>>>(clu);
    scan_k<<<1, 1024>>>(0);
    scan_k<<<1, 1024>>>(1);
    copy_cursors_k<<<196, 256>>>();
    fill_edges_k<<<3125, 256>>>(src, dst);
    fill_clusters_k<<<196, 256>>>(clu);

    const int aggBlocks = (N_NODES * 32 + 255) / 256;  // warp per node

    // layer 0
    mlp_k<64, NW, NB><<<GRID_SMS, NW * 32, smem0>>>(x, P[0], P[1], P[2], P[3], P[4], P[5]);
    agg_k<64><<<aggBlocks, 256>>>();
    // layer 1
    mlp_k<128, NW, NB><<<GRID_SMS, NW * 32, smem1>>>(x, P[6], P[7], P[8], P[9], P[10], P[11]);
    agg_k<128><<<aggBlocks, 256>>>();
    // layer 2
    mlp_k<256, NW, NB><<<GRID_SMS, NW * 32, smem2>>>(x, P[12], P[13], P[14], P[15], P[16], P[17]);
    agg_k<256><<<aggBlocks, 256>>>();

    // pooling + column L2 normalization
    pool_k<<<(N_CLUST * 32 + 255) / 256, 256>>>();
    colsum_k<<<64, 512>>>();
    norm_k<<<1, 512>>>();
    scale_k<<<(N_CLUST * 512 + 255) / 256, 256>>>(out);
}